// round 1
// baseline (speedup 1.0000x reference)
#include <cuda_runtime.h>
#include <cuda_bf16.h>
#include <cstdint>

// One CTA per batch row b (B=4096). 256 threads, 8 samples/thread (n=2048).
// Stage the 8x8x8 voxel window (all samples of a row provably land inside it,
// since |bound_psf| < half < 2.5 and ix = p*256/255 - 0.5) into SMEM with
// zero-fill for out-of-bounds voxels (matches the reference's validity mask).

#define SPAN 8
#define NTHREADS 256

__global__ __launch_bounds__(NTHREADS)
void select_profile_kernel(
    const float* __restrict__ vol,       // [256,256,256]
    const float* __restrict__ sg,        // [B,3]
    const float* __restrict__ ax,        // [B,1,6]
    const float* __restrict__ bound,     // [B,2,3]
    const float* __restrict__ icov,      // [B,3,3]
    const float* __restrict__ xyz,       // [B,n,3]
    float* __restrict__ out,             // [B]
    int n)
{
    __shared__ float sv[SPAN * SPAN * SPAN];
    __shared__ float rnum[NTHREADS / 32];
    __shared__ float rden[NTHREADS / 32];

    const int b   = blockIdx.x;
    const int tid = threadIdx.x;

    // ---- per-row parameters (computed redundantly by all threads) ----
    const float vx = ax[b * 6 + 0], vy = ax[b * 6 + 1], vz = ax[b * 6 + 2];
    const float Tx = ax[b * 6 + 3], Ty = ax[b * 6 + 4], Tz = ax[b * 6 + 5];

    const float th  = sqrtf(vx * vx + vy * vy + vz * vz + 1e-12f);
    const float itn = 1.0f / th;
    const float kx = vx * itn, ky = vy * itn, kz = vz * itn;
    float s, cth;
    __sincosf(th, &s, &cth);
    const float c = 1.0f - cth;

    // Rodrigues: R = I + s*K + c*(k k^T - I)
    const float R00 = 1.0f + c * (kx * kx - 1.0f);
    const float R01 = -s * kz + c * kx * ky;
    const float R02 =  s * ky + c * kx * kz;
    const float R10 =  s * kz + c * kx * ky;
    const float R11 = 1.0f + c * (ky * ky - 1.0f);
    const float R12 = -s * kx + c * ky * kz;
    const float R20 = -s * ky + c * kx * kz;
    const float R21 =  s * kx + c * ky * kz;
    const float R22 = 1.0f + c * (kz * kz - 1.0f);

    const float px = sg[b * 3 + 0] + Tx;
    const float py = sg[b * 3 + 1] + Ty;
    const float pz = sg[b * 3 + 2] + Tz;

    const float cx = R00 * px + R01 * py + R02 * pz;
    const float cy = R10 * px + R11 * py + R12 * pz;
    const float cz = R20 * px + R21 * py + R22 * pz;

    const float hx = (bound[b * 6 + 3] - bound[b * 6 + 0]) * 0.5f;
    const float hy = (bound[b * 6 + 4] - bound[b * 6 + 1]) * 0.5f;
    const float hz = (bound[b * 6 + 5] - bound[b * 6 + 2]) * 0.5f;

    // ix = (c + bp) * 256/255 - 0.5   (derived from grid_sample formula, W=H=D=256)
    const float SCL = 256.0f / 255.0f;
    const float cx2 = cx * SCL - 0.5f;
    const float cy2 = cy * SCL - 0.5f;
    const float cz2 = cz * SCL - 0.5f;
    const float hSx = hx * SCL, hSy = hy * SCL, hSz = hz * SCL;

    const int lox = (int)floorf(cx2 - hSx - 0.001f);
    const int loy = (int)floorf(cy2 - hSy - 0.001f);
    const int loz = (int)floorf(cz2 - hSz - 0.001f);

    // ---- stage the 8^3 window into SMEM (zero for OOB voxels) ----
    #pragma unroll
    for (int idx = tid; idx < SPAN * SPAN * SPAN; idx += NTHREADS) {
        const int xg = lox + (idx & 7);
        const int yg = loy + ((idx >> 3) & 7);
        const int zg = loz + (idx >> 6);
        float v = 0.0f;
        if ((unsigned)xg < 256u && (unsigned)yg < 256u && (unsigned)zg < 256u)
            v = __ldg(&vol[((size_t)zg * 256 + yg) * 256 + xg]);
        sv[idx] = v;
    }
    __syncthreads();

    // quadratic form coefficients (symmetrized exactly)
    const float* M = icov + (size_t)b * 9;
    const float M00 = M[0], M11 = M[4], M22 = M[8];
    const float S01 = M[1] + M[3];
    const float S02 = M[2] + M[6];
    const float S12 = M[5] + M[7];

    const float flox = (float)lox, floy = (float)loy, floz = (float)loz;

    float num = 0.0f, den = 0.0f;

    for (int base = tid * 8; base < n; base += NTHREADS * 8) {
        // 8 samples * 3 floats = 24 floats = 6 float4 (16B-aligned: base%8==0)
        const float4* p4 = (const float4*)(xyz + ((size_t)b * n + base) * 3);
        float buf[24];
        #pragma unroll
        for (int j = 0; j < 6; j++) {
            const float4 t4 = p4[j];
            buf[4 * j + 0] = t4.x;
            buf[4 * j + 1] = t4.y;
            buf[4 * j + 2] = t4.z;
            buf[4 * j + 3] = t4.w;
        }

        #pragma unroll
        for (int i = 0; i < 8; i++) {
            const float tx = buf[3 * i + 0];
            const float ty = buf[3 * i + 1];
            const float tz = buf[3 * i + 2];

            // 2*sigmoid(t)-1 = (1 - e^-t)/(1 + e^-t)
            const float ex = __expf(-tx);
            const float ey = __expf(-ty);
            const float ez = __expf(-tz);
            const float sx = __fdividef(1.0f - ex, 1.0f + ex);
            const float sy = __fdividef(1.0f - ey, 1.0f + ey);
            const float sz = __fdividef(1.0f - ez, 1.0f + ez);

            const float bx = sx * hx;
            const float by = sy * hy;
            const float bz = sz * hz;

            // local (window-relative) sample coords, guaranteed >= 0
            const float lxf = fmaf(bx, SCL, cx2) - flox;
            const float lyf = fmaf(by, SCL, cy2) - floy;
            const float lzf = fmaf(bz, SCL, cz2) - floz;

            int x0 = (int)lxf; if (x0 > SPAN - 2) x0 = SPAN - 2;
            int y0 = (int)lyf; if (y0 > SPAN - 2) y0 = SPAN - 2;
            int z0 = (int)lzf; if (z0 > SPAN - 2) z0 = SPAN - 2;
            const float fx = lxf - (float)x0;
            const float fy = lyf - (float)y0;
            const float fz = lzf - (float)z0;

            const int bi = (z0 * SPAN + y0) * SPAN + x0;
            const float v000 = sv[bi];
            const float v001 = sv[bi + 1];
            const float v010 = sv[bi + SPAN];
            const float v011 = sv[bi + SPAN + 1];
            const float v100 = sv[bi + SPAN * SPAN];
            const float v101 = sv[bi + SPAN * SPAN + 1];
            const float v110 = sv[bi + SPAN * SPAN + SPAN];
            const float v111 = sv[bi + SPAN * SPAN + SPAN + 1];

            const float c00 = fmaf(fx, v001 - v000, v000);
            const float c01 = fmaf(fx, v011 - v010, v010);
            const float c10 = fmaf(fx, v101 - v100, v100);
            const float c11 = fmaf(fx, v111 - v110, v110);
            const float c0  = fmaf(fy, c01 - c00, c00);
            const float c1  = fmaf(fy, c11 - c10, c10);
            const float pv  = fmaf(fz, c1 - c0, c0);

            // q = bp^T M bp (symmetrized)
            const float q = bx * fmaf(M00, bx, fmaf(S01, by, S02 * bz))
                          + by * fmaf(M11, by, S12 * bz)
                          + bz * (M22 * bz);
            const float w = __expf(-0.5f * q);

            num = fmaf(pv, w, num);
            den += w;
        }
    }

    // ---- reduction: warp shuffle, then cross-warp via SMEM ----
    #pragma unroll
    for (int o = 16; o > 0; o >>= 1) {
        num += __shfl_xor_sync(0xFFFFFFFFu, num, o);
        den += __shfl_xor_sync(0xFFFFFFFFu, den, o);
    }
    if ((tid & 31) == 0) {
        rnum[tid >> 5] = num;
        rden[tid >> 5] = den;
    }
    __syncthreads();
    if (tid == 0) {
        float N = 0.0f, Dn = 0.0f;
        #pragma unroll
        for (int i = 0; i < NTHREADS / 32; i++) { N += rnum[i]; Dn += rden[i]; }
        out[b] = N / Dn;
    }
}

extern "C" void kernel_launch(void* const* d_in, const int* in_sizes, int n_in,
                              void* d_out, int out_size) {
    const float* vol   = (const float*)d_in[0];  // x [1,1,256,256,256]
    const float* sg    = (const float*)d_in[1];  // sampleGrid [B,3]
    const float* ax    = (const float*)d_in[2];  // ax [B,1,6]
    const float* bound = (const float*)d_in[3];  // bound [B,2,3]
    const float* icov  = (const float*)d_in[4];  // InvCovScaled [B,3,3]
    // d_in[5] = psf_sigma (unused by reference)
    const float* xyz   = (const float*)d_in[6];  // xyz_psf [B,n,3]
    float* out = (float*)d_out;

    const int B = in_sizes[1] / 3;
    const int n = in_sizes[6] / (B * 3);

    select_profile_kernel<<<B, NTHREADS>>>(vol, sg, ax, bound, icov, xyz, out, n);
}

// round 2
// speedup vs baseline: 1.0442x; 1.0442x over previous
#include <cuda_runtime.h>
#include <cuda_bf16.h>
#include <cstdint>

// One CTA per batch row b (B=4096), 256 threads, 8 samples/thread (n=2048).
// All samples of a row land in an 8^3 voxel window (|bound_psf| < 2.5 scaled).
// Window staged to SMEM twice: scalar sv[512], then tap-pair float4 layout
// sv4[z][y][x] = (v[x], v[x+1], v[x,y+1], v[x+1,y+1]) so trilinear = 2x LDS.128.

#define SPAN 8
#define NTHREADS 256
#define SCL (256.0f / 255.0f)

__device__ __forceinline__ float tanh_fast(float x) {
    float y;
    asm("tanh.approx.f32 %0, %1;" : "=f"(y) : "f"(x));
    return y;
}

__global__ __launch_bounds__(NTHREADS)
void select_profile_kernel(
    const float* __restrict__ vol,       // [256,256,256]
    const float* __restrict__ sg,        // [B,3]
    const float* __restrict__ ax,        // [B,1,6]
    const float* __restrict__ bound,     // [B,2,3]
    const float* __restrict__ icov,      // [B,3,3]
    const float* __restrict__ xyz,       // [B,n,3]
    float* __restrict__ out,             // [B]
    int n)
{
    __shared__ float  sv[SPAN * SPAN * SPAN];          // 2 KB
    __shared__ float4 sv4[SPAN * 7 * 7];               // 6.3 KB
    __shared__ float  prm[12];
    __shared__ int    wlo[3];
    __shared__ float  rnum[NTHREADS / 32];
    __shared__ float  rden[NTHREADS / 32];

    const int b   = blockIdx.x;
    const int tid = threadIdx.x;

    // ---- per-row parameters: thread 0 only, broadcast via SMEM ----
    if (tid == 0) {
        const float vx = ax[b * 6 + 0], vy = ax[b * 6 + 1], vz = ax[b * 6 + 2];
        const float Tx = ax[b * 6 + 3], Ty = ax[b * 6 + 4], Tz = ax[b * 6 + 5];

        const float th  = sqrtf(vx * vx + vy * vy + vz * vz + 1e-12f);
        const float itn = 1.0f / th;
        const float kx = vx * itn, ky = vy * itn, kz = vz * itn;
        float s, cth;
        __sincosf(th, &s, &cth);
        const float c = 1.0f - cth;

        const float R00 = 1.0f + c * (kx * kx - 1.0f);
        const float R01 = -s * kz + c * kx * ky;
        const float R02 =  s * ky + c * kx * kz;
        const float R10 =  s * kz + c * kx * ky;
        const float R11 = 1.0f + c * (ky * ky - 1.0f);
        const float R12 = -s * kx + c * ky * kz;
        const float R20 = -s * ky + c * kx * kz;
        const float R21 =  s * kx + c * ky * kz;
        const float R22 = 1.0f + c * (kz * kz - 1.0f);

        const float px = sg[b * 3 + 0] + Tx;
        const float py = sg[b * 3 + 1] + Ty;
        const float pz = sg[b * 3 + 2] + Tz;

        const float cx = R00 * px + R01 * py + R02 * pz;
        const float cy = R10 * px + R11 * py + R12 * pz;
        const float cz = R20 * px + R21 * py + R22 * pz;

        const float hx = (bound[b * 6 + 3] - bound[b * 6 + 0]) * 0.5f;
        const float hy = (bound[b * 6 + 4] - bound[b * 6 + 1]) * 0.5f;
        const float hz = (bound[b * 6 + 5] - bound[b * 6 + 2]) * 0.5f;

        const float cx2 = cx * SCL - 0.5f;
        const float cy2 = cy * SCL - 0.5f;
        const float cz2 = cz * SCL - 0.5f;

        const int lox = (int)floorf(cx2 - hx * SCL - 0.01f);
        const int loy = (int)floorf(cy2 - hy * SCL - 0.01f);
        const int loz = (int)floorf(cz2 - hz * SCL - 0.01f);

        prm[0] = cx2 - (float)lox;   // window-local center
        prm[1] = cy2 - (float)loy;
        prm[2] = cz2 - (float)loz;
        prm[3] = hx; prm[4] = hy; prm[5] = hz;

        const float* M = icov + (size_t)b * 9;
        prm[6]  = M[0];          // M00
        prm[7]  = M[4];          // M11
        prm[8]  = M[8];          // M22
        prm[9]  = M[1] + M[3];   // S01
        prm[10] = M[2] + M[6];   // S02
        prm[11] = M[5] + M[7];   // S12

        wlo[0] = lox; wlo[1] = loy; wlo[2] = loz;
    }
    __syncthreads();

    // ---- stage scalar 8^3 window (zero-fill OOB) ----
    const int lox = wlo[0], loy = wlo[1], loz = wlo[2];
    #pragma unroll
    for (int idx = tid; idx < SPAN * SPAN * SPAN; idx += NTHREADS) {
        const int xg = lox + (idx & 7);
        const int yg = loy + ((idx >> 3) & 7);
        const int zg = loz + (idx >> 6);
        float v = 0.0f;
        if ((unsigned)xg < 256u && (unsigned)yg < 256u && (unsigned)zg < 256u)
            v = __ldg(&vol[((size_t)zg * 256 + yg) * 256 + xg]);
        sv[idx] = v;
    }
    __syncthreads();

    // ---- build tap-pair float4 layout: sv4[(z*7+y)*7+x] ----
    #pragma unroll
    for (int idx = tid; idx < SPAN * 7 * 7; idx += NTHREADS) {
        const int x = idx % 7;
        const int zy = idx / 7;
        const int y = zy % 7;
        const int z = zy / 7;
        const int s = (z * SPAN + y) * SPAN + x;
        sv4[idx] = make_float4(sv[s], sv[s + 1], sv[s + SPAN], sv[s + SPAN + 1]);
    }
    __syncthreads();

    const float cxl = prm[0], cyl = prm[1], czl = prm[2];
    const float hx  = prm[3], hy  = prm[4], hz  = prm[5];
    const float M00 = prm[6], M11 = prm[7], M22 = prm[8];
    const float S01 = prm[9], S02 = prm[10], S12 = prm[11];

    float num = 0.0f, den = 0.0f;

    for (int base = tid * 8; base < n; base += NTHREADS * 8) {
        const float4* p4 = (const float4*)(xyz + ((size_t)b * n + base) * 3);

        #pragma unroll
        for (int half = 0; half < 2; half++) {
            // 4 samples = 12 floats = 3 aligned float4 (streaming loads)
            const float4 q0 = __ldcs(p4 + half * 3 + 0);
            const float4 q1 = __ldcs(p4 + half * 3 + 1);
            const float4 q2 = __ldcs(p4 + half * 3 + 2);
            const float buf[12] = { q0.x, q0.y, q0.z, q0.w,
                                    q1.x, q1.y, q1.z, q1.w,
                                    q2.x, q2.y, q2.z, q2.w };

            #pragma unroll
            for (int i = 0; i < 4; i++) {
                // 2*sigmoid(t) - 1 = tanh(t/2)
                const float bx = tanh_fast(0.5f * buf[3 * i + 0]) * hx;
                const float by = tanh_fast(0.5f * buf[3 * i + 1]) * hy;
                const float bz = tanh_fast(0.5f * buf[3 * i + 2]) * hz;

                // window-local coords (>= ~0.006 by margin)
                const float lxf = fmaf(bx, SCL, cxl);
                const float lyf = fmaf(by, SCL, cyl);
                const float lzf = fmaf(bz, SCL, czl);

                const float x0f = fminf(fmaxf(floorf(lxf), 0.0f), 6.0f);
                const float y0f = fminf(fmaxf(floorf(lyf), 0.0f), 6.0f);
                const float z0f = fminf(fmaxf(floorf(lzf), 0.0f), 6.0f);
                const float fx = lxf - x0f;
                const float fy = lyf - y0f;
                const float fz = lzf - z0f;

                const int bi = (int)fmaf(fmaf(z0f, 7.0f, y0f), 7.0f, x0f);
                const float4 a0 = sv4[bi];         // z0  : v000 v001 v010 v011
                const float4 a1 = sv4[bi + 49];    // z0+1: v100 v101 v110 v111

                const float c00 = fmaf(fx, a0.y - a0.x, a0.x);
                const float c01 = fmaf(fx, a0.w - a0.z, a0.z);
                const float c10 = fmaf(fx, a1.y - a1.x, a1.x);
                const float c11 = fmaf(fx, a1.w - a1.z, a1.z);
                const float c0  = fmaf(fy, c01 - c00, c00);
                const float c1  = fmaf(fy, c11 - c10, c10);
                const float pv  = fmaf(fz, c1 - c0, c0);

                // q = bp^T M bp (symmetrized)
                const float t1 = fmaf(M00, bx, fmaf(S01, by, S02 * bz));
                const float t2 = fmaf(M11, by, S12 * bz);
                const float q  = fmaf(bx, t1, fmaf(by, t2, bz * (M22 * bz)));
                const float w  = __expf(-0.5f * q);

                num = fmaf(pv, w, num);
                den += w;
            }
        }
    }

    // ---- reduction ----
    #pragma unroll
    for (int o = 16; o > 0; o >>= 1) {
        num += __shfl_xor_sync(0xFFFFFFFFu, num, o);
        den += __shfl_xor_sync(0xFFFFFFFFu, den, o);
    }
    if ((tid & 31) == 0) {
        rnum[tid >> 5] = num;
        rden[tid >> 5] = den;
    }
    __syncthreads();
    if (tid == 0) {
        float N = 0.0f, Dn = 0.0f;
        #pragma unroll
        for (int i = 0; i < NTHREADS / 32; i++) { N += rnum[i]; Dn += rden[i]; }
        out[b] = N / Dn;
    }
}

extern "C" void kernel_launch(void* const* d_in, const int* in_sizes, int n_in,
                              void* d_out, int out_size) {
    const float* vol   = (const float*)d_in[0];  // x [1,1,256,256,256]
    const float* sg    = (const float*)d_in[1];  // sampleGrid [B,3]
    const float* ax    = (const float*)d_in[2];  // ax [B,1,6]
    const float* bound = (const float*)d_in[3];  // bound [B,2,3]
    const float* icov  = (const float*)d_in[4];  // InvCovScaled [B,3,3]
    // d_in[5] = psf_sigma (unused by reference)
    const float* xyz   = (const float*)d_in[6];  // xyz_psf [B,n,3]
    float* out = (float*)d_out;

    const int B = in_sizes[1] / 3;
    const int n = in_sizes[6] / (B * 3);

    select_profile_kernel<<<B, NTHREADS>>>(vol, sg, ax, bound, icov, xyz, out, n);
}

// round 3
// speedup vs baseline: 1.0719x; 1.0265x over previous
#include <cuda_runtime.h>
#include <cuda_bf16.h>
#include <cstdint>

// One CTA per batch row b (B=4096), 256 threads, 8 samples/thread (n=2048).
// All samples of a row land in an 8^3 voxel window (|bound_psf|*SCL < 2.52,
// margin 0.02). Window staged directly into tap-pair float4 layout:
// sv4[(z*7+y)*7+x] = (v[x,y], v[x+1,y], v[x,y+1], v[x+1,y+1]) at depth z,
// so trilinear = 2x LDS.128 (z and z+1).

#define SPAN 8
#define NTHREADS 256
#define SCL (256.0f / 255.0f)

__device__ __forceinline__ float tanh_fast(float x) {
    float y;
    asm("tanh.approx.f32 %0, %1;" : "=f"(y) : "f"(x));
    return y;
}

__global__ __launch_bounds__(NTHREADS, 4)
void select_profile_kernel(
    const float* __restrict__ vol,       // [256,256,256]
    const float* __restrict__ sg,        // [B,3]
    const float* __restrict__ ax,        // [B,1,6]
    const float* __restrict__ bound,     // [B,2,3]
    const float* __restrict__ icov,      // [B,3,3]
    const float* __restrict__ xyz,       // [B,n,3]
    float* __restrict__ out,             // [B]
    int n)
{
    __shared__ float4 sv4[SPAN * 7 * 7];               // 6.3 KB
    __shared__ float  rnum[NTHREADS / 32];
    __shared__ float  rden[NTHREADS / 32];

    const int b   = blockIdx.x;
    const int tid = threadIdx.x;

    // ---- prefetch this thread's 8 samples (24 floats = 6 float4) NOW ----
    // Consumed only after window staging + barrier: DRAM latency fully hidden.
    const int base = tid * 8;
    float4 q0, q1, q2, q3, q4, q5;
    if (base < n) {
        const float4* p4 = (const float4*)(xyz + ((size_t)b * n + base) * 3);
        q0 = __ldcs(p4 + 0); q1 = __ldcs(p4 + 1); q2 = __ldcs(p4 + 2);
        q3 = __ldcs(p4 + 3); q4 = __ldcs(p4 + 4); q5 = __ldcs(p4 + 5);
    } else {
        q0 = q1 = q2 = q3 = q4 = q5 = make_float4(0.f, 0.f, 0.f, 0.f);
    }

    // ---- per-row parameters (redundant in every thread; broadcast L1 hits) ----
    const float vx = __ldg(&ax[b * 6 + 0]), vy = __ldg(&ax[b * 6 + 1]), vz = __ldg(&ax[b * 6 + 2]);
    const float Tx = __ldg(&ax[b * 6 + 3]), Ty = __ldg(&ax[b * 6 + 4]), Tz = __ldg(&ax[b * 6 + 5]);

    const float th  = sqrtf(vx * vx + vy * vy + vz * vz + 1e-12f);
    const float itn = 1.0f / th;
    const float kx = vx * itn, ky = vy * itn, kz = vz * itn;
    float s, cth;
    __sincosf(th, &s, &cth);
    const float c = 1.0f - cth;

    const float R00 = 1.0f + c * (kx * kx - 1.0f);
    const float R01 = -s * kz + c * kx * ky;
    const float R02 =  s * ky + c * kx * kz;
    const float R10 =  s * kz + c * kx * ky;
    const float R11 = 1.0f + c * (ky * ky - 1.0f);
    const float R12 = -s * kx + c * ky * kz;
    const float R20 = -s * ky + c * kx * kz;
    const float R21 =  s * kx + c * ky * kz;
    const float R22 = 1.0f + c * (kz * kz - 1.0f);

    const float px = __ldg(&sg[b * 3 + 0]) + Tx;
    const float py = __ldg(&sg[b * 3 + 1]) + Ty;
    const float pz = __ldg(&sg[b * 3 + 2]) + Tz;

    const float cxw = R00 * px + R01 * py + R02 * pz;
    const float cyw = R10 * px + R11 * py + R12 * pz;
    const float czw = R20 * px + R21 * py + R22 * pz;

    const float hx = (__ldg(&bound[b * 6 + 3]) - __ldg(&bound[b * 6 + 0])) * 0.5f;
    const float hy = (__ldg(&bound[b * 6 + 4]) - __ldg(&bound[b * 6 + 1])) * 0.5f;
    const float hz = (__ldg(&bound[b * 6 + 5]) - __ldg(&bound[b * 6 + 2])) * 0.5f;

    const float cx2 = cxw * SCL - 0.5f;
    const float cy2 = cyw * SCL - 0.5f;
    const float cz2 = czw * SCL - 0.5f;

    const int lox = (int)floorf(cx2 - hx * SCL - 0.02f);
    const int loy = (int)floorf(cy2 - hy * SCL - 0.02f);
    const int loz = (int)floorf(cz2 - hz * SCL - 0.02f);

    const float cxl = cx2 - (float)lox;   // window-local center, >= 0.02
    const float cyl = cy2 - (float)loy;
    const float czl = cz2 - (float)loz;

    const float* M = icov + (size_t)b * 9;
    const float M00 = __ldg(M + 0), M11 = __ldg(M + 4), M22 = __ldg(M + 8);
    const float S01 = __ldg(M + 1) + __ldg(M + 3);
    const float S02 = __ldg(M + 2) + __ldg(M + 6);
    const float S12 = __ldg(M + 5) + __ldg(M + 7);

    // ---- build tap-pair window directly from global (L1-resident reuse) ----
    #pragma unroll
    for (int idx = tid; idx < SPAN * 7 * 7; idx += NTHREADS) {
        const int x = idx % 7;
        const int zy = idx / 7;
        const int y = zy % 7;
        const int z = zy / 7;
        const int xg = lox + x, yg = loy + y, zg = loz + z;

        const bool zin = (unsigned)zg < 256u;
        const bool x0in = (unsigned)xg < 256u;
        const bool x1in = (unsigned)(xg + 1) < 256u;
        const bool y0in = (unsigned)yg < 256u;
        const bool y1in = (unsigned)(yg + 1) < 256u;
        const size_t rbase = ((size_t)zg * 256 + yg) * 256 + xg;

        float4 t = make_float4(0.f, 0.f, 0.f, 0.f);
        if (zin) {
            if (x0in && y0in) t.x = __ldg(vol + rbase);
            if (x1in && y0in) t.y = __ldg(vol + rbase + 1);
            if (x0in && y1in) t.z = __ldg(vol + rbase + 256);
            if (x1in && y1in) t.w = __ldg(vol + rbase + 257);
        }
        sv4[idx] = t;
    }
    __syncthreads();

    float num = 0.0f, den = 0.0f;

    if (base < n) {
        const float bufx[8] = { q0.x, q0.w, q1.z, q2.y, q3.x, q3.w, q4.z, q5.y };
        const float bufy[8] = { q0.y, q1.x, q1.w, q2.z, q3.y, q4.x, q4.w, q5.z };
        const float bufz[8] = { q0.z, q1.y, q2.x, q2.w, q3.z, q4.y, q5.x, q5.w };

        #pragma unroll
        for (int i = 0; i < 8; i++) {
            // 2*sigmoid(t) - 1 = tanh(t/2)
            const float bx = tanh_fast(0.5f * bufx[i]) * hx;
            const float by = tanh_fast(0.5f * bufy[i]) * hy;
            const float bz = tanh_fast(0.5f * bufz[i]) * hz;

            // window-local coords; provably in [0.013, 6.08] -> floor in [0,6]
            const float lxf = fmaf(bx, SCL, cxl);
            const float lyf = fmaf(by, SCL, cyl);
            const float lzf = fmaf(bz, SCL, czl);

            const float x0f = floorf(lxf);
            const float y0f = floorf(lyf);
            const float z0f = floorf(lzf);
            const float fx = lxf - x0f;
            const float fy = lyf - y0f;
            const float fz = lzf - z0f;

            const int bi = (int)fmaf(fmaf(z0f, 7.0f, y0f), 7.0f, x0f);
            const float4 a0 = sv4[bi];         // z0  : v000 v001 v010 v011
            const float4 a1 = sv4[bi + 49];    // z0+1: v100 v101 v110 v111

            const float c00 = fmaf(fx, a0.y - a0.x, a0.x);
            const float c01 = fmaf(fx, a0.w - a0.z, a0.z);
            const float c10 = fmaf(fx, a1.y - a1.x, a1.x);
            const float c11 = fmaf(fx, a1.w - a1.z, a1.z);
            const float c0  = fmaf(fy, c01 - c00, c00);
            const float c1  = fmaf(fy, c11 - c10, c10);
            const float pv  = fmaf(fz, c1 - c0, c0);

            // q = bp^T M bp (symmetrized)
            const float t1 = fmaf(M00, bx, fmaf(S01, by, S02 * bz));
            const float t2 = fmaf(M11, by, S12 * bz);
            const float qf = fmaf(bx, t1, fmaf(by, t2, bz * (M22 * bz)));
            const float w  = __expf(-0.5f * qf);

            num = fmaf(pv, w, num);
            den += w;
        }
    }

    // general-n fallback (no-op for n = NTHREADS*8 = 2048)
    for (int bb = NTHREADS * 8 + tid * 8; bb < n; bb += NTHREADS * 8) {
        const float4* p4 = (const float4*)(xyz + ((size_t)b * n + bb) * 3);
        float4 r0 = __ldcs(p4 + 0), r1 = __ldcs(p4 + 1), r2 = __ldcs(p4 + 2),
               r3 = __ldcs(p4 + 3), r4 = __ldcs(p4 + 4), r5 = __ldcs(p4 + 5);
        const float bufa[24] = { r0.x, r0.y, r0.z, r0.w, r1.x, r1.y, r1.z, r1.w,
                                 r2.x, r2.y, r2.z, r2.w, r3.x, r3.y, r3.z, r3.w,
                                 r4.x, r4.y, r4.z, r4.w, r5.x, r5.y, r5.z, r5.w };
        #pragma unroll
        for (int i = 0; i < 8; i++) {
            const float bx = tanh_fast(0.5f * bufa[3 * i + 0]) * hx;
            const float by = tanh_fast(0.5f * bufa[3 * i + 1]) * hy;
            const float bz = tanh_fast(0.5f * bufa[3 * i + 2]) * hz;
            const float lxf = fmaf(bx, SCL, cxl);
            const float lyf = fmaf(by, SCL, cyl);
            const float lzf = fmaf(bz, SCL, czl);
            const float x0f = floorf(lxf), y0f = floorf(lyf), z0f = floorf(lzf);
            const float fx = lxf - x0f, fy = lyf - y0f, fz = lzf - z0f;
            const int bi = (int)fmaf(fmaf(z0f, 7.0f, y0f), 7.0f, x0f);
            const float4 a0 = sv4[bi];
            const float4 a1 = sv4[bi + 49];
            const float c00 = fmaf(fx, a0.y - a0.x, a0.x);
            const float c01 = fmaf(fx, a0.w - a0.z, a0.z);
            const float c10 = fmaf(fx, a1.y - a1.x, a1.x);
            const float c11 = fmaf(fx, a1.w - a1.z, a1.z);
            const float c0  = fmaf(fy, c01 - c00, c00);
            const float c1  = fmaf(fy, c11 - c10, c10);
            const float pv  = fmaf(fz, c1 - c0, c0);
            const float t1 = fmaf(M00, bx, fmaf(S01, by, S02 * bz));
            const float t2 = fmaf(M11, by, S12 * bz);
            const float qf = fmaf(bx, t1, fmaf(by, t2, bz * (M22 * bz)));
            const float w  = __expf(-0.5f * qf);
            num = fmaf(pv, w, num);
            den += w;
        }
    }

    // ---- reduction ----
    #pragma unroll
    for (int o = 16; o > 0; o >>= 1) {
        num += __shfl_xor_sync(0xFFFFFFFFu, num, o);
        den += __shfl_xor_sync(0xFFFFFFFFu, den, o);
    }
    if ((tid & 31) == 0) {
        rnum[tid >> 5] = num;
        rden[tid >> 5] = den;
    }
    __syncthreads();
    if (tid == 0) {
        float N = 0.0f, Dn = 0.0f;
        #pragma unroll
        for (int i = 0; i < NTHREADS / 32; i++) { N += rnum[i]; Dn += rden[i]; }
        out[b] = N / Dn;
    }
}

extern "C" void kernel_launch(void* const* d_in, const int* in_sizes, int n_in,
                              void* d_out, int out_size) {
    const float* vol   = (const float*)d_in[0];  // x [1,1,256,256,256]
    const float* sg    = (const float*)d_in[1];  // sampleGrid [B,3]
    const float* ax    = (const float*)d_in[2];  // ax [B,1,6]
    const float* bound = (const float*)d_in[3];  // bound [B,2,3]
    const float* icov  = (const float*)d_in[4];  // InvCovScaled [B,3,3]
    // d_in[5] = psf_sigma (unused by reference)
    const float* xyz   = (const float*)d_in[6];  // xyz_psf [B,n,3]
    float* out = (float*)d_out;

    const int B = in_sizes[1] / 3;
    const int n = in_sizes[6] / (B * 3);

    select_profile_kernel<<<B, NTHREADS>>>(vol, sg, ax, bound, icov, xyz, out, n);
}